// round 1
// baseline (speedup 1.0000x reference)
#include <cuda_runtime.h>

#define BATCH 2
#define C     48
#define C3    144
#define DD    32
#define HD    64
#define WD    64
#define LL    (DD*HD*WD)   /* 131072 */
#define HW    (HD*WD)      /* 4096 */
#define HEADS 6
#define CPH   8

// ---- scratch (static device arrays; no runtime allocation) ----
__device__ float g_qkv[(size_t)BATCH * C3 * LL];   // after 1x1x1 conv
__device__ float g_dw [(size_t)BATCH * C3 * LL];   // after depthwise conv
__device__ float g_attn[BATCH * HEADS * CPH * CPH];
__device__ float g_weff[BATCH * C * C];

// ---------------------------------------------------------------------------
// K0: zero the attention accumulator
// ---------------------------------------------------------------------------
__global__ void k0_zero() {
    g_attn[threadIdx.x] = 0.0f;
}

// ---------------------------------------------------------------------------
// K1: qkv = W1[144x48] * x[48xL] + b1    (per batch)
// block = 288 threads, tile = 64 l-positions, all 144 out channels
// ---------------------------------------------------------------------------
__global__ __launch_bounds__(288) void k1_qkv(const float* __restrict__ x,
                                              const float* __restrict__ w1,
                                              const float* __restrict__ b1) {
    __shared__ float  Wt[48][144];   // [ic][oc]
    __shared__ float4 Xs[48][16];    // [ic][l/4]

    const int b  = blockIdx.y;
    const int l0 = blockIdx.x * 64;
    const int tid = threadIdx.x;

    for (int i = tid; i < C3 * C; i += 288) {
        int oc = i / 48, ic = i % 48;
        Wt[ic][oc] = w1[i];
    }
    float* xs = (float*)Xs;
    for (int i = tid; i < 48 * 64; i += 288) {
        int ic = i >> 6, j = i & 63;
        xs[ic * 64 + j] = x[((size_t)b * C + ic) * LL + l0 + j];
    }
    __syncthreads();

    const int lq  = tid & 15;        // 0..15 -> 4 l's each
    const int og  = tid >> 4;        // 0..17 -> 8 oc's each
    const int oc0 = og * 8;

    float4 acc[8];
#pragma unroll
    for (int j = 0; j < 8; j++) acc[j] = make_float4(0.f, 0.f, 0.f, 0.f);

#pragma unroll 4
    for (int ic = 0; ic < 48; ic++) {
        const float4 xv = Xs[ic][lq];
        const float4 wa = *(const float4*)&Wt[ic][oc0];
        const float4 wb = *(const float4*)&Wt[ic][oc0 + 4];
        const float wr[8] = {wa.x, wa.y, wa.z, wa.w, wb.x, wb.y, wb.z, wb.w};
#pragma unroll
        for (int j = 0; j < 8; j++) {
            acc[j].x += wr[j] * xv.x;
            acc[j].y += wr[j] * xv.y;
            acc[j].z += wr[j] * xv.z;
            acc[j].w += wr[j] * xv.w;
        }
    }

#pragma unroll
    for (int j = 0; j < 8; j++) {
        const int oc = oc0 + j;
        const float bb = b1[oc];
        float4 v = acc[j];
        v.x += bb; v.y += bb; v.z += bb; v.w += bb;
        *(float4*)&g_qkv[((size_t)b * C3 + oc) * LL + l0 + lq * 4] = v;
    }
}

// ---------------------------------------------------------------------------
// K2: depthwise 3x3x3 SAME conv over all 144 channels.
// One warp per (b, ch, h); lane covers 2 w's (float2); rolls along d keeping a
// 3x3 register window of rows; W-shifts via warp shuffles (zero at edges).
// ---------------------------------------------------------------------------
__global__ __launch_bounds__(256) void k2_dw(const float* __restrict__ wdw,
                                             const float* __restrict__ bdw) {
    const int gw   = blockIdx.x * 8 + (threadIdx.x >> 5);
    const int lane = threadIdx.x & 31;
    const int h  = gw % HD;
    const int t  = gw / HD;
    const int ch = t % C3;
    const int b  = t / C3;

    const float* base = g_qkv + ((size_t)b * C3 + ch) * LL;
    float*       obase = g_dw + ((size_t)b * C3 + ch) * LL;

    float w[27];
#pragma unroll
    for (int i = 0; i < 27; i++) w[i] = wdw[ch * 27 + i];
    const float bias = bdw[ch];

    float2 r[3][3];  // [dd][hh] rows, each lane holds w=2*lane,2*lane+1

    auto loadrow = [&](int d, int hh) -> float2 {
        const int hr = h + hh - 1;
        if (d < 0 || d >= DD || hr < 0 || hr >= HD) return make_float2(0.f, 0.f);
        return ((const float2*)(base + (size_t)d * HW + hr * WD))[lane];
    };

#pragma unroll
    for (int hh = 0; hh < 3; hh++) {
        r[0][hh] = make_float2(0.f, 0.f);
        r[1][hh] = loadrow(0, hh);
        r[2][hh] = loadrow(1, hh);
    }

    for (int d = 0; d < DD; d++) {
        float2 o = make_float2(bias, bias);
#pragma unroll
        for (int dd = 0; dd < 3; dd++) {
#pragma unroll
            for (int hh = 0; hh < 3; hh++) {
                const float2 rv = r[dd][hh];
                float xm = __shfl_up_sync(0xffffffffu, rv.y, 1);
                if (lane == 0) xm = 0.f;
                float xp = __shfl_down_sync(0xffffffffu, rv.x, 1);
                if (lane == 31) xp = 0.f;
                const int tb = (dd * 3 + hh) * 3;
                const float w0 = w[tb], w1 = w[tb + 1], w2 = w[tb + 2];
                o.x += w0 * xm   + w1 * rv.x + w2 * rv.y;
                o.y += w0 * rv.x + w1 * rv.y + w2 * xp;
            }
        }
        ((float2*)(obase + (size_t)d * HW + h * WD))[lane] = o;
#pragma unroll
        for (int hh = 0; hh < 3; hh++) {
            r[0][hh] = r[1][hh];
            r[1][hh] = r[2][hh];
            r[2][hh] = loadrow(d + 2, hh);
        }
    }
}

// ---------------------------------------------------------------------------
// K3: attn[b,h,c,d] += sum_l q[b,h,c,l] * k[b,h,d,l]   (raw dots, no scale)
// grid = (L/4096 chunks, B*HEADS); block = 256, 64 accumulators/thread
// ---------------------------------------------------------------------------
__global__ __launch_bounds__(256) void k3_attn() {
    const int chunk = blockIdx.x;
    const int bh = blockIdx.y;
    const int b = bh / HEADS, hd = bh % HEADS;

    const float* qb = g_dw + ((size_t)b * C3 + hd * CPH) * LL + chunk * 4096;
    const float* kb = g_dw + ((size_t)b * C3 + C + hd * CPH) * LL + chunk * 4096;

    float acc[64];
#pragma unroll
    for (int i = 0; i < 64; i++) acc[i] = 0.f;

    for (int it = 0; it < 16; it++) {
        const int l = it * 256 + threadIdx.x;
        float q[8], k[8];
#pragma unroll
        for (int i = 0; i < 8; i++) {
            q[i] = qb[(size_t)i * LL + l];
            k[i] = kb[(size_t)i * LL + l];
        }
#pragma unroll
        for (int i = 0; i < 8; i++)
#pragma unroll
            for (int j = 0; j < 8; j++)
                acc[i * 8 + j] += q[i] * k[j];
    }

    __shared__ float red[64];
    if (threadIdx.x < 64) red[threadIdx.x] = 0.f;
    __syncthreads();
    const int lane = threadIdx.x & 31;
#pragma unroll
    for (int v = 0; v < 64; v++) {
        float s = acc[v];
#pragma unroll
        for (int off = 16; off > 0; off >>= 1)
            s += __shfl_xor_sync(0xffffffffu, s, off);
        if (lane == 0) atomicAdd(&red[v], s);
    }
    __syncthreads();
    if (threadIdx.x < 64)
        atomicAdd(&g_attn[bh * 64 + threadIdx.x], red[threadIdx.x]);
}

// ---------------------------------------------------------------------------
// K4: softmax(scale*attn + mask) then fold proj:
//     Weff[b][oc][h*8+j] = sum_i w_proj[oc][h*8+i] * attn_soft[b][h][i][j]
// ---------------------------------------------------------------------------
__global__ __launch_bounds__(256) void k4_soft(const float* __restrict__ mask,
                                               const float* __restrict__ wproj) {
    const int tid = threadIdx.x;
    __shared__ float A[BATCH * HEADS * CPH * CPH];
    const float scale = 0.40824829046386307f;  // 6^-0.5

    if (tid < BATCH * HEADS * CPH) {  // 96 rows
        const int b = tid / (HEADS * CPH);
        const int r = tid % (HEADS * CPH);
        const int hd = r / CPH, c = r % CPH;
        float v[8];
        float mx = -1e30f;
#pragma unroll
        for (int j = 0; j < 8; j++) {
            v[j] = g_attn[((b * HEADS + hd) * CPH + c) * CPH + j] * scale
                 + mask[(b * CPH + c) * CPH + j];
            mx = fmaxf(mx, v[j]);
        }
        float s = 0.f;
#pragma unroll
        for (int j = 0; j < 8; j++) { v[j] = expf(v[j] - mx); s += v[j]; }
        const float inv = 1.f / s;
#pragma unroll
        for (int j = 0; j < 8; j++)
            A[((b * HEADS + hd) * CPH + c) * CPH + j] = v[j] * inv;
    }
    __syncthreads();

    for (int i = tid; i < BATCH * C * C; i += 256) {
        const int b = i / (C * C);
        const int r = i % (C * C);
        const int oc = r / C, c2 = r % C;
        const int hd = c2 / CPH, j = c2 % CPH;
        float s = 0.f;
#pragma unroll
        for (int ii = 0; ii < 8; ii++)
            s += wproj[oc * C + hd * CPH + ii]
               * A[((b * HEADS + hd) * CPH + ii) * CPH + j];
        g_weff[i] = s;
    }
}

// ---------------------------------------------------------------------------
// K5: out[48,L] = Weff[b][48x48] * v_dw[48,L] + b_proj
// block = 192 threads, tile = 128 l
// ---------------------------------------------------------------------------
__global__ __launch_bounds__(192) void k5_proj(const float* __restrict__ bproj,
                                               float* __restrict__ outp) {
    __shared__ float  Wt[48][48];    // [c2][oc]
    __shared__ float4 Vs[48][32];    // [c2][l/4]

    const int b  = blockIdx.y;
    const int l0 = blockIdx.x * 128;
    const int tid = threadIdx.x;

    for (int i = tid; i < C * C; i += 192) {
        int oc = i / 48, c2 = i % 48;
        Wt[c2][oc] = g_weff[b * C * C + i];
    }
    float* vs = (float*)Vs;
    for (int i = tid; i < 48 * 128; i += 192) {
        int ic = i >> 7, j = i & 127;
        vs[ic * 128 + j] = g_dw[((size_t)b * C3 + 2 * C + ic) * LL + l0 + j];
    }
    __syncthreads();

    const int lq  = tid & 31;   // 0..31 -> 4 l's each
    const int og  = tid >> 5;   // 0..5  -> 8 oc's each
    const int oc0 = og * 8;

    float4 acc[8];
#pragma unroll
    for (int j = 0; j < 8; j++) acc[j] = make_float4(0.f, 0.f, 0.f, 0.f);

#pragma unroll 4
    for (int c2 = 0; c2 < 48; c2++) {
        const float4 xv = Vs[c2][lq];
        const float4 wa = *(const float4*)&Wt[c2][oc0];
        const float4 wb = *(const float4*)&Wt[c2][oc0 + 4];
        const float wr[8] = {wa.x, wa.y, wa.z, wa.w, wb.x, wb.y, wb.z, wb.w};
#pragma unroll
        for (int j = 0; j < 8; j++) {
            acc[j].x += wr[j] * xv.x;
            acc[j].y += wr[j] * xv.y;
            acc[j].z += wr[j] * xv.z;
            acc[j].w += wr[j] * xv.w;
        }
    }

#pragma unroll
    for (int j = 0; j < 8; j++) {
        const int oc = oc0 + j;
        const float bb = bproj[oc];
        float4 v = acc[j];
        v.x += bb; v.y += bb; v.z += bb; v.w += bb;
        *(float4*)&outp[((size_t)b * C + oc) * LL + l0 + lq * 4] = v;
    }
}

// ---------------------------------------------------------------------------
extern "C" void kernel_launch(void* const* d_in, const int* in_sizes, int n_in,
                              void* d_out, int out_size) {
    const float* x      = (const float*)d_in[0];
    const float* mask   = (const float*)d_in[1];
    const float* w_qkv1 = (const float*)d_in[2];
    const float* b_qkv1 = (const float*)d_in[3];
    const float* w_dw   = (const float*)d_in[4];
    const float* b_dw   = (const float*)d_in[5];
    const float* w_proj = (const float*)d_in[6];
    const float* b_proj = (const float*)d_in[7];
    float* out = (float*)d_out;

    k0_zero<<<1, BATCH * HEADS * CPH * CPH>>>();
    k1_qkv<<<dim3(LL / 64, BATCH), 288>>>(x, w_qkv1, b_qkv1);
    k2_dw<<<(BATCH * C3 * HD) / 8, 256>>>(w_dw, b_dw);
    k3_attn<<<dim3(LL / 4096, BATCH * HEADS), 256>>>();
    k4_soft<<<1, 256>>>(mask, w_proj);
    k5_proj<<<dim3(LL / 128, BATCH), 192>>>(b_proj, out);
}

// round 2
// speedup vs baseline: 1.0214x; 1.0214x over previous
#include <cuda_runtime.h>

#define BATCH 2
#define C     48
#define C3    144
#define DD    32
#define HD    64
#define WD    64
#define LL    (DD*HD*WD)   /* 131072 */
#define HW    (HD*WD)      /* 4096 */
#define HEADS 6
#define CPH   8

// ---- scratch (static device arrays; no runtime allocation) ----
__device__ float g_qkv[(size_t)BATCH * C3 * LL];   // after 1x1x1 conv
__device__ float g_dw [(size_t)BATCH * C3 * LL];   // after depthwise conv
__device__ float g_attn[BATCH * HEADS * CPH * CPH];
__device__ float g_weff[BATCH * C * C];

// ---------------------------------------------------------------------------
// K0: zero the attention accumulator
// ---------------------------------------------------------------------------
__global__ void k0_zero() {
    g_attn[threadIdx.x] = 0.0f;
}

// ---------------------------------------------------------------------------
// K1: qkv = W1[144x48] * x[48xL] + b1    (per batch)
// block = 288 threads; W loaded once, then 4 phases of 64 l each (tile 256)
// ---------------------------------------------------------------------------
__global__ __launch_bounds__(288) void k1_qkv(const float* __restrict__ x,
                                              const float* __restrict__ w1,
                                              const float* __restrict__ b1) {
    __shared__ float  Wt[48][144];   // [ic][oc]
    __shared__ float4 Xs[48][16];    // [ic][l/4]

    const int b  = blockIdx.y;
    const size_t l0 = (size_t)blockIdx.x * 256;
    const int tid = threadIdx.x;

    for (int i = tid; i < C3 * C; i += 288) {
        int oc = i / 48, ic = i % 48;
        Wt[ic][oc] = w1[i];
    }

    const int lq  = tid & 15;        // 0..15 -> 4 l's each (one float4)
    const int og  = tid >> 4;        // 0..17 -> 8 oc's each
    const int oc0 = og * 8;

#pragma unroll 1
    for (int phase = 0; phase < 4; phase++) {
        const size_t lp = l0 + phase * 64;
        __syncthreads();  // Wt ready / previous phase compute done
        for (int i = tid; i < 48 * 16; i += 288) {
            int ic = i >> 4, j = i & 15;
            Xs[ic][j] = *(const float4*)(x + ((size_t)b * C + ic) * LL + lp + j * 4);
        }
        __syncthreads();

        float4 acc[8];
#pragma unroll
        for (int j = 0; j < 8; j++) acc[j] = make_float4(0.f, 0.f, 0.f, 0.f);

#pragma unroll 4
        for (int ic = 0; ic < 48; ic++) {
            const float4 xv = Xs[ic][lq];
            const float4 wa = *(const float4*)&Wt[ic][oc0];
            const float4 wb = *(const float4*)&Wt[ic][oc0 + 4];
            const float wr[8] = {wa.x, wa.y, wa.z, wa.w, wb.x, wb.y, wb.z, wb.w};
#pragma unroll
            for (int j = 0; j < 8; j++) {
                acc[j].x += wr[j] * xv.x;
                acc[j].y += wr[j] * xv.y;
                acc[j].z += wr[j] * xv.z;
                acc[j].w += wr[j] * xv.w;
            }
        }

#pragma unroll
        for (int j = 0; j < 8; j++) {
            const int oc = oc0 + j;
            const float bb = b1[oc];
            float4 v = acc[j];
            v.x += bb; v.y += bb; v.z += bb; v.w += bb;
            *(float4*)&g_qkv[((size_t)b * C3 + oc) * LL + lp + lq * 4] = v;
        }
    }
}

// ---------------------------------------------------------------------------
// K2: depthwise 3x3x3 SAME conv over all 144 channels.
// One warp per (b, ch, h); lane covers 2 w's (float2); rolls along d keeping a
// 3x3 register window of rows. Edge values (W-shifts) are computed by warp
// shuffle ONCE at row-load time and cached alongside the row.
// ---------------------------------------------------------------------------
__global__ __launch_bounds__(256) void k2_dw(const float* __restrict__ wdw,
                                             const float* __restrict__ bdw) {
    const int gw   = blockIdx.x * 8 + (threadIdx.x >> 5);
    const int lane = threadIdx.x & 31;
    const int h  = gw % HD;
    const int t  = gw / HD;
    const int ch = t % C3;
    const int b  = t / C3;

    const float* base  = g_qkv + ((size_t)b * C3 + ch) * LL;
    float*       obase = g_dw  + ((size_t)b * C3 + ch) * LL;

    float w[27];
#pragma unroll
    for (int i = 0; i < 27; i++) w[i] = wdw[ch * 27 + i];
    const float bias = bdw[ch];

    float2 rv[3][3];   // [slot][hh] row values (w = 2*lane, 2*lane+1)
    float  rl[3][3];   // value at w-1 (shuffled in once)
    float  rr[3][3];   // value at w+2 (shuffled in once)

    auto loadrow = [&](int d, int hh, int s) {
        const int hr = h + hh - 1;
        float2 v2;
        if (d < 0 || d >= DD || hr < 0 || hr >= HD) v2 = make_float2(0.f, 0.f);
        else v2 = ((const float2*)(base + (size_t)d * HW + hr * WD))[lane];
        float a = __shfl_up_sync(0xffffffffu, v2.y, 1);
        if (lane == 0) a = 0.f;
        float p = __shfl_down_sync(0xffffffffu, v2.x, 1);
        if (lane == 31) p = 0.f;
        rv[s][hh] = v2; rl[s][hh] = a; rr[s][hh] = p;
    };

#pragma unroll
    for (int hh = 0; hh < 3; hh++) {
        rv[0][hh] = make_float2(0.f, 0.f); rl[0][hh] = 0.f; rr[0][hh] = 0.f;
        loadrow(0, hh, 1);
        loadrow(1, hh, 2);
    }

    for (int d = 0; d < DD; d++) {
        float2 o = make_float2(bias, bias);
#pragma unroll
        for (int dd = 0; dd < 3; dd++) {
#pragma unroll
            for (int hh = 0; hh < 3; hh++) {
                const int tb = (dd * 3 + hh) * 3;
                const float w0 = w[tb], w1 = w[tb + 1], w2 = w[tb + 2];
                const float2 v2 = rv[dd][hh];
                o.x += w0 * rl[dd][hh] + w1 * v2.x + w2 * v2.y;
                o.y += w0 * v2.x       + w1 * v2.y + w2 * rr[dd][hh];
            }
        }
        ((float2*)(obase + (size_t)d * HW + h * WD))[lane] = o;
#pragma unroll
        for (int hh = 0; hh < 3; hh++) {
            rv[0][hh] = rv[1][hh]; rl[0][hh] = rl[1][hh]; rr[0][hh] = rr[1][hh];
            rv[1][hh] = rv[2][hh]; rl[1][hh] = rl[2][hh]; rr[1][hh] = rr[2][hh];
            loadrow(d + 2, hh, 2);
        }
    }
}

// ---------------------------------------------------------------------------
// K3: attn[b,h,c,d] += sum_l q[b,h,c,l] * k[b,h,d,l]   (raw dots, no scale)
// grid = (L/8192 chunks, B*HEADS); block = 256; float2 loads (2 l per iter)
// ---------------------------------------------------------------------------
__global__ __launch_bounds__(256) void k3_attn() {
    const int chunk = blockIdx.x;
    const int bh = blockIdx.y;
    const int b = bh / HEADS, hd = bh % HEADS;

    const float* qb = g_dw + ((size_t)b * C3 + hd * CPH) * LL + (size_t)chunk * 8192;
    const float* kb = qb + (size_t)C * LL;

    float acc[64];
#pragma unroll
    for (int i = 0; i < 64; i++) acc[i] = 0.f;

    for (int it = 0; it < 16; it++) {
        const int l2 = it * 256 + threadIdx.x;   // float2 index within chunk
        float2 q[8], k[8];
#pragma unroll
        for (int i = 0; i < 8; i++) {
            q[i] = ((const float2*)(qb + (size_t)i * LL))[l2];
            k[i] = ((const float2*)(kb + (size_t)i * LL))[l2];
        }
#pragma unroll
        for (int i = 0; i < 8; i++)
#pragma unroll
            for (int j = 0; j < 8; j++)
                acc[i * 8 + j] += q[i].x * k[j].x + q[i].y * k[j].y;
    }

    __shared__ float red[64];
    if (threadIdx.x < 64) red[threadIdx.x] = 0.f;
    __syncthreads();
    const int lane = threadIdx.x & 31;
#pragma unroll
    for (int v = 0; v < 64; v++) {
        float s = acc[v];
#pragma unroll
        for (int off = 16; off > 0; off >>= 1)
            s += __shfl_xor_sync(0xffffffffu, s, off);
        if (lane == 0) atomicAdd(&red[v], s);
    }
    __syncthreads();
    if (threadIdx.x < 64)
        atomicAdd(&g_attn[bh * 64 + threadIdx.x], red[threadIdx.x]);
}

// ---------------------------------------------------------------------------
// K4: softmax(scale*attn + mask) then fold proj:
//     Weff[b][oc][h*8+j] = sum_i w_proj[oc][h*8+i] * attn_soft[b][h][i][j]
// ---------------------------------------------------------------------------
__global__ __launch_bounds__(256) void k4_soft(const float* __restrict__ mask,
                                               const float* __restrict__ wproj) {
    const int tid = threadIdx.x;
    __shared__ float A[BATCH * HEADS * CPH * CPH];
    const float scale = 0.40824829046386307f;  // 6^-0.5

    if (tid < BATCH * HEADS * CPH) {  // 96 rows
        const int b = tid / (HEADS * CPH);
        const int r = tid % (HEADS * CPH);
        const int hd = r / CPH, c = r % CPH;
        float v[8];
        float mx = -1e30f;
#pragma unroll
        for (int j = 0; j < 8; j++) {
            v[j] = g_attn[((b * HEADS + hd) * CPH + c) * CPH + j] * scale
                 + mask[(b * CPH + c) * CPH + j];
            mx = fmaxf(mx, v[j]);
        }
        float s = 0.f;
#pragma unroll
        for (int j = 0; j < 8; j++) { v[j] = expf(v[j] - mx); s += v[j]; }
        const float inv = 1.f / s;
#pragma unroll
        for (int j = 0; j < 8; j++)
            A[((b * HEADS + hd) * CPH + c) * CPH + j] = v[j] * inv;
    }
    __syncthreads();

    for (int i = tid; i < BATCH * C * C; i += 256) {
        const int b = i / (C * C);
        const int r = i % (C * C);
        const int oc = r / C, c2 = r % C;
        const int hd = c2 / CPH, j = c2 % CPH;
        float s = 0.f;
#pragma unroll
        for (int ii = 0; ii < 8; ii++)
            s += wproj[oc * C + hd * CPH + ii]
               * A[((b * HEADS + hd) * CPH + ii) * CPH + j];
        g_weff[i] = s;
    }
}

// ---------------------------------------------------------------------------
// K5: out[48,L] = Weff[b][48x48] * v_dw[48,L] + b_proj
// block = 192 threads; W loaded once, 2 phases of 128 l (tile 256)
// ---------------------------------------------------------------------------
__global__ __launch_bounds__(192) void k5_proj(const float* __restrict__ bproj,
                                               float* __restrict__ outp) {
    __shared__ float  Wt[48][48];    // [c2][oc]
    __shared__ float4 Vs[48][32];    // [c2][l/4]

    const int b  = blockIdx.y;
    const size_t l0 = (size_t)blockIdx.x * 256;
    const int tid = threadIdx.x;

    for (int i = tid; i < C * C; i += 192) {
        int oc = i / 48, c2 = i % 48;
        Wt[c2][oc] = g_weff[b * C * C + i];
    }

    const int lq  = tid & 31;   // 0..31 -> 4 l's each (one float4)
    const int og  = tid >> 5;   // 0..5  -> 8 oc's each
    const int oc0 = og * 8;

#pragma unroll 1
    for (int phase = 0; phase < 2; phase++) {
        const size_t lp = l0 + phase * 128;
        __syncthreads();
        for (int i = tid; i < 48 * 32; i += 192) {
            int ic = i >> 5, j = i & 31;
            Vs[ic][j] = *(const float4*)(g_dw + ((size_t)b * C3 + 2 * C + ic) * LL + lp + j * 4);
        }
        __syncthreads();

        float4 acc[8];
#pragma unroll
        for (int j = 0; j < 8; j++) acc[j] = make_float4(0.f, 0.f, 0.f, 0.f);

#pragma unroll 4
        for (int c2 = 0; c2 < 48; c2++) {
            const float4 xv = Vs[c2][lq];
            const float4 wa = *(const float4*)&Wt[c2][oc0];
            const float4 wb = *(const float4*)&Wt[c2][oc0 + 4];
            const float wr[8] = {wa.x, wa.y, wa.z, wa.w, wb.x, wb.y, wb.z, wb.w};
#pragma unroll
            for (int j = 0; j < 8; j++) {
                acc[j].x += wr[j] * xv.x;
                acc[j].y += wr[j] * xv.y;
                acc[j].z += wr[j] * xv.z;
                acc[j].w += wr[j] * xv.w;
            }
        }

#pragma unroll
        for (int j = 0; j < 8; j++) {
            const int oc = oc0 + j;
            const float bb = bproj[oc];
            float4 v = acc[j];
            v.x += bb; v.y += bb; v.z += bb; v.w += bb;
            *(float4*)&outp[((size_t)b * C + oc) * LL + lp + lq * 4] = v;
        }
    }
}

// ---------------------------------------------------------------------------
extern "C" void kernel_launch(void* const* d_in, const int* in_sizes, int n_in,
                              void* d_out, int out_size) {
    const float* x      = (const float*)d_in[0];
    const float* mask   = (const float*)d_in[1];
    const float* w_qkv1 = (const float*)d_in[2];
    const float* b_qkv1 = (const float*)d_in[3];
    const float* w_dw   = (const float*)d_in[4];
    const float* b_dw   = (const float*)d_in[5];
    const float* w_proj = (const float*)d_in[6];
    const float* b_proj = (const float*)d_in[7];
    float* out = (float*)d_out;

    k0_zero<<<1, BATCH * HEADS * CPH * CPH>>>();
    k1_qkv<<<dim3(LL / 256, BATCH), 288>>>(x, w_qkv1, b_qkv1);
    k2_dw<<<(BATCH * C3 * HD) / 8, 256>>>(w_dw, b_dw);
    k3_attn<<<dim3(LL / 8192, BATCH * HEADS), 256>>>();
    k4_soft<<<1, 256>>>(mask, w_proj);
    k5_proj<<<dim3(LL / 256, BATCH), 192>>>(b_proj, out);
}